// round 8
// baseline (speedup 1.0000x reference)
#include <cuda_runtime.h>

// Fused pansharpening loss:
//   loss = mean|gauss5x5_reflect(out) - ms|
//        + mean|sobelx(mean_c(out), zeropad) - sobelx(pan, zeropad)|
//        + mean|sobely(mean_c(out), zeropad) - sobely(pan, zeropad)|
// Shapes: pan [8,1,512,512], ms [8,8,512,512], out [8,8,512,512], fp32. Output: scalar fp32.

namespace {
constexpr int Himg = 512, Wimg = 512, Cc = 8, Nb = 8;
constexpr int TILE_W = 64, TILE_H = 32;
constexpr int SW = 68;            // 64 + 2*2 halo, multiple of 4 for float4 LDS
constexpr int SH = 36;            // 32 + 2*2 halo
constexpr int SN = SW * SH;       // 2448
constexpr int NTH = 128;          // 16 x-threads * 8 y-threads; each thread owns 4x4 px
constexpr int GX = Wimg / TILE_W; // 8
constexpr int GY = Himg / TILE_H; // 16
constexpr int NBLK = GX * GY * Nb; // 1024  (<= 148 SMs * 7 CTAs/SM: single wave)
// Gaussian 5-tap, sigma=2, normalized (matches cv2 GaussianBlur((5,5),2))
constexpr float G0 = 0.15246914f;
constexpr float G1 = 0.22184130f;
constexpr float G2 = 0.25137913f;
}

__device__ float g_part[NBLK * 3];

__device__ __forceinline__ int refl(int i) {
    // reflect-101 for pad<=2 on a 512 axis: -k -> k, 511+k -> 511-k
    i = (i < 0) ? -i : i;
    return (i >= 512) ? (1022 - i) : i;
}

__global__ __launch_bounds__(NTH, 7) void loss_main_kernel(
    const float* __restrict__ pan,
    const float* __restrict__ ms,
    const float* __restrict__ outp)
{
    __shared__ __align__(16) float s_out[SN];   // current channel of `out`, reflect-padded
    __shared__ __align__(16) float s_mean[SN];  // channel-sum of `out`, zero outside image
    __shared__ __align__(16) float s_pan[SN];   // pan tile, zero outside image
    __shared__ float s_red[4][3];

    const int x0 = blockIdx.x * TILE_W;
    const int y0 = blockIdx.y * TILE_H;
    const int n  = blockIdx.z;
    const int tid = threadIdx.x;
    const int tx = tid & 15;
    const int ty = tid >> 4;
    const int bx = tx << 2;   // first of 4 output cols for this thread
    const int by = ty << 2;   // first of 4 output rows for this thread

    // ---- init: pan tile (zero-pad) + zero mean tile ----
    const float* panb = pan + n * (Himg * Wimg);
    #pragma unroll 4
    for (int idx = tid; idx < SN; idx += NTH) {
        int r  = idx / SW;
        int cl = idx - r * SW;
        int gy = y0 + r - 2, gx = x0 + cl - 2;
        bool inb = ((unsigned)gy < (unsigned)Himg) && ((unsigned)gx < (unsigned)Wimg);
        s_pan[idx]  = inb ? panb[gy * Wimg + gx] : 0.0f;
        s_mean[idx] = 0.0f;
    }

    const float gw[5] = {G0, G1, G2, G1, G0};
    float acc_ms = 0.0f;

    // ---- per-channel: load tile, accumulate channel-sum, separable blur, |.-ms| ----
    for (int c = 0; c < Cc; ++c) {
        __syncthreads();   // protect s_out from previous iteration's readers
        const float* oc = outp + (n * Cc + c) * (Himg * Wimg);
        #pragma unroll 4
        for (int idx = tid; idx < SN; idx += NTH) {
            int r  = idx / SW;
            int cl = idx - r * SW;
            int gy = y0 + r - 2, gx = x0 + cl - 2;
            float v = oc[refl(gy) * Wimg + refl(gx)];
            s_out[idx] = v;
            if (((unsigned)gy < (unsigned)Himg) && ((unsigned)gx < (unsigned)Wimg))
                s_mean[idx] += v;   // each idx owned by one thread: race-free
        }
        __syncthreads();

        float bacc[4][4];
        #pragma unroll
        for (int i = 0; i < 4; ++i)
            #pragma unroll
            for (int j = 0; j < 4; ++j) bacc[i][j] = 0.0f;

        // horizontal 5-tap over 8 rows (4 outputs + 4 halo), vertical accumulate
        #pragma unroll
        for (int r = 0; r < 8; ++r) {
            const float4* rowp = reinterpret_cast<const float4*>(s_out) + (by + r) * (SW / 4);
            float4 a = rowp[tx];
            float4 b = rowp[tx + 1];
            float v[8] = {a.x, a.y, a.z, a.w, b.x, b.y, b.z, b.w};
            float hb[4];
            #pragma unroll
            for (int j = 0; j < 4; ++j)
                hb[j] = G0 * v[j] + G1 * v[j + 1] + G2 * v[j + 2]
                      + G1 * v[j + 3] + G0 * v[j + 4];
            #pragma unroll
            for (int i = 0; i < 4; ++i) {
                int k = r - i;
                if (k >= 0 && k <= 4) {
                    float w = gw[k];
                    #pragma unroll
                    for (int j = 0; j < 4; ++j) bacc[i][j] += w * hb[j];
                }
            }
        }

        const float* mc = ms + (n * Cc + c) * (Himg * Wimg);
        #pragma unroll
        for (int i = 0; i < 4; ++i) {
            float4 m4 = *reinterpret_cast<const float4*>(
                &mc[(y0 + by + i) * Wimg + x0 + bx]);
            acc_ms += fabsf(bacc[i][0] - m4.x) + fabsf(bacc[i][1] - m4.y)
                    + fabsf(bacc[i][2] - m4.z) + fabsf(bacc[i][3] - m4.w);
        }
    }

    __syncthreads();   // s_mean complete

    // ---- Sobel on channel-mean (=sum*0.125) vs pan, both zero-padded ----
    float acc_gx = 0.0f, acc_gy = 0.0f;
    #pragma unroll
    for (int i = 0; i < 4; ++i) {
        float m[3][8], p[3][8];
        #pragma unroll
        for (int dy = 0; dy < 3; ++dy) {
            int srow = by + i + 1 + dy;
            const float4* mr = reinterpret_cast<const float4*>(s_mean) + srow * (SW / 4);
            const float4* pr = reinterpret_cast<const float4*>(s_pan)  + srow * (SW / 4);
            float4 a = mr[tx], b = mr[tx + 1];
            m[dy][0]=a.x; m[dy][1]=a.y; m[dy][2]=a.z; m[dy][3]=a.w;
            m[dy][4]=b.x; m[dy][5]=b.y; m[dy][6]=b.z; m[dy][7]=b.w;
            float4 e = pr[tx], f = pr[tx + 1];
            p[dy][0]=e.x; p[dy][1]=e.y; p[dy][2]=e.z; p[dy][3]=e.w;
            p[dy][4]=f.x; p[dy][5]=f.y; p[dy][6]=f.z; p[dy][7]=f.w;
        }
        #pragma unroll
        for (int j = 0; j < 4; ++j) {
            float ogx = (m[0][j+3] + 2.0f*m[1][j+3] + m[2][j+3])
                      - (m[0][j+1] + 2.0f*m[1][j+1] + m[2][j+1]);
            float ogy = (m[2][j+1] + 2.0f*m[2][j+2] + m[2][j+3])
                      - (m[0][j+1] + 2.0f*m[0][j+2] + m[0][j+3]);
            float pgx = (p[0][j+3] + 2.0f*p[1][j+3] + p[2][j+3])
                      - (p[0][j+1] + 2.0f*p[1][j+1] + p[2][j+1]);
            float pgy = (p[2][j+1] + 2.0f*p[2][j+2] + p[2][j+3])
                      - (p[0][j+1] + 2.0f*p[0][j+2] + p[0][j+3]);
            acc_gx += fabsf(0.125f * ogx - pgx);
            acc_gy += fabsf(0.125f * ogy - pgy);
        }
    }

    // ---- block reduction -> deterministic per-block partials ----
    #pragma unroll
    for (int off = 16; off; off >>= 1) {
        acc_ms += __shfl_xor_sync(0xffffffffu, acc_ms, off);
        acc_gx += __shfl_xor_sync(0xffffffffu, acc_gx, off);
        acc_gy += __shfl_xor_sync(0xffffffffu, acc_gy, off);
    }
    int warp = tid >> 5, lane = tid & 31;
    if (lane == 0) {
        s_red[warp][0] = acc_ms; s_red[warp][1] = acc_gx; s_red[warp][2] = acc_gy;
    }
    __syncthreads();
    if (tid == 0) {
        float a = 0.0f, b = 0.0f, c2 = 0.0f;
        #pragma unroll
        for (int w = 0; w < 4; ++w) { a += s_red[w][0]; b += s_red[w][1]; c2 += s_red[w][2]; }
        int bid = (blockIdx.z * GY + blockIdx.y) * GX + blockIdx.x;
        g_part[bid * 3 + 0] = a;
        g_part[bid * 3 + 1] = b;
        g_part[bid * 3 + 2] = c2;
    }
}

__global__ __launch_bounds__(NBLK) void loss_final_kernel(float* __restrict__ outp)
{
    __shared__ float sr[32][3];
    int t = threadIdx.x;           // NBLK == 1024 threads, one per block partial
    float a = g_part[t * 3 + 0];
    float b = g_part[t * 3 + 1];
    float c = g_part[t * 3 + 2];
    #pragma unroll
    for (int off = 16; off; off >>= 1) {
        a += __shfl_xor_sync(0xffffffffu, a, off);
        b += __shfl_xor_sync(0xffffffffu, b, off);
        c += __shfl_xor_sync(0xffffffffu, c, off);
    }
    int warp = t >> 5, lane = t & 31;
    if (lane == 0) { sr[warp][0] = a; sr[warp][1] = b; sr[warp][2] = c; }
    __syncthreads();
    if (t < 32) {
        a = sr[t][0]; b = sr[t][1]; c = sr[t][2];
        #pragma unroll
        for (int off = 16; off; off >>= 1) {
            a += __shfl_xor_sync(0xffffffffu, a, off);
            b += __shfl_xor_sync(0xffffffffu, b, off);
            c += __shfl_xor_sync(0xffffffffu, c, off);
        }
        if (t == 0) {
            // loss = acc_ms / (N*C*H*W) + (acc_gx + acc_gy) / (N*H*W)
            outp[0] = a * (1.0f / 16777216.0f) + (b + c) * (1.0f / 2097152.0f);
        }
    }
}

extern "C" void kernel_launch(void* const* d_in, const int* in_sizes, int n_in,
                              void* d_out, int out_size)
{
    // Expected order: pan [2097152], ms [16777216], out [16777216].
    // Defensive: locate pan by its unique size; the two big tensors keep order ms, out.
    const float* pan = (const float*)d_in[0];
    const float* ms  = (const float*)d_in[1];
    const float* outp= (const float*)d_in[2];
    if (n_in == 3 && in_sizes[0] != 2097152) {
        const float* big[2]; int nb = 0;
        for (int i = 0; i < 3; ++i) {
            if (in_sizes[i] == 2097152) pan = (const float*)d_in[i];
            else if (nb < 2) big[nb++] = (const float*)d_in[i];
        }
        if (nb == 2) { ms = big[0]; outp = big[1]; }
    }

    dim3 grid(GX, GY, Nb);
    loss_main_kernel<<<grid, NTH>>>(pan, ms, outp);
    loss_final_kernel<<<1, NBLK>>>((float*)d_out);
}

// round 13
// speedup vs baseline: 1.1188x; 1.1188x over previous
#include <cuda_runtime.h>

// Fused pansharpening loss (single kernel, last-block final reduction):
//   loss = mean|gauss5x5_reflect(out) - ms|
//        + mean|sobelx(mean_c(out), zeropad) - sobelx(pan, zeropad)|
//        + mean|sobely(mean_c(out), zeropad) - sobely(pan, zeropad)|
// Shapes: pan [8,1,512,512], ms [8,8,512,512], out [8,8,512,512], fp32. Output: scalar fp32.

namespace {
constexpr int Himg = 512, Wimg = 512, Cc = 8, Nb = 8;
constexpr int TILE_W = 64, TILE_H = 32;
constexpr int SW = 68;            // 64 + 2*2 halo, multiple of 4
constexpr int SH = 36;            // 32 + 2*2 halo
constexpr int SN = SW * SH;       // 2448 floats
constexpr int NPAIR = SN / 2;     // 1224 float2 slots (34 pairs/row)
constexpr int PPR = SW / 2;       // 34 pairs per row
constexpr int NTH = 128;          // 16 x * 8 y threads; each owns 4x4 px
constexpr int GX = Wimg / TILE_W; // 8
constexpr int GY = Himg / TILE_H; // 16
constexpr int NBLK = GX * GY * Nb; // 1024 (<= 148*7: single wave)
// Gaussian 5-tap, sigma=2, normalized (matches cv2 GaussianBlur((5,5),2))
constexpr float G0 = 0.15246914f;
constexpr float G1 = 0.22184130f;
constexpr float G2 = 0.25137913f;
}

__device__ float g_part[NBLK * 3];
__device__ unsigned int g_count;   // zero-initialized; reset by last block each launch

__device__ __forceinline__ int refl(int i) {
    // reflect-101 for pad<=2 on a 512 axis: -k -> k, 511+k -> 511-k
    i = (i < 0) ? -i : i;
    return (i >= 512) ? (1022 - i) : i;
}

__global__ __launch_bounds__(NTH, 7) void loss_main_kernel(
    const float* __restrict__ pan,
    const float* __restrict__ ms,
    const float* __restrict__ outp,
    float* __restrict__ lossp)
{
    __shared__ __align__(16) float s_out[SN];   // current channel of `out`, reflect-padded
    __shared__ __align__(16) float s_mean[SN];  // channel-sum of `out`, zero outside image
    __shared__ __align__(16) float s_pan[SN];   // pan tile, zero outside image
    __shared__ float s_red[4][3];
    __shared__ int s_last;

    const int x0 = blockIdx.x * TILE_W;
    const int y0 = blockIdx.y * TILE_H;
    const int n  = blockIdx.z;
    const int tid = threadIdx.x;
    const int tx = tid & 15;
    const int ty = tid >> 4;
    const int bx = tx << 2;   // first of 4 output cols for this thread
    const int by = ty << 2;   // first of 4 output rows for this thread

    // ---- init: pan tile (zero-pad) + zero mean tile, float2 granularity ----
    const float* panb = pan + n * (Himg * Wimg);
    #pragma unroll 4
    for (int idx = tid; idx < NPAIR; idx += NTH) {
        int r  = idx / PPR;
        int pp = idx - r * PPR;
        int gy = y0 + r - 2;
        int gx = x0 + pp * 2 - 2;
        float2 pv = make_float2(0.0f, 0.0f);
        if ((unsigned)gy < (unsigned)Himg) {
            if (gx >= 0 && gx < Wimg - 1) {
                pv = *reinterpret_cast<const float2*>(panb + gy * Wimg + gx);
            } else {
                if ((unsigned)gx < (unsigned)Wimg)       pv.x = panb[gy * Wimg + gx];
                if ((unsigned)(gx + 1) < (unsigned)Wimg) pv.y = panb[gy * Wimg + gx + 1];
            }
        }
        *reinterpret_cast<float2*>(s_pan  + r * SW + pp * 2) = pv;
        *reinterpret_cast<float2*>(s_mean + r * SW + pp * 2) = make_float2(0.0f, 0.0f);
    }

    const float gw[5] = {G0, G1, G2, G1, G0};
    float acc_ms = 0.0f;

    // ---- per-channel: float2 tile load + channel-sum, separable blur, |.-ms| ----
    for (int c = 0; c < Cc; ++c) {
        __syncthreads();   // protect s_out from previous iteration's readers
        const float* oc = outp + (n * Cc + c) * (Himg * Wimg);
        #pragma unroll 4
        for (int idx = tid; idx < NPAIR; idx += NTH) {
            int r  = idx / PPR;
            int pp = idx - r * PPR;
            int gy = y0 + r - 2;
            int gx = x0 + pp * 2 - 2;
            const float* orow = oc + refl(gy) * Wimg;
            float2 v;
            if (gx >= 0 && gx < Wimg - 1) {          // vector-safe (row reflect only)
                v = *reinterpret_cast<const float2*>(orow + gx);
            } else {                                  // horizontal reflect: scalar
                v.x = orow[refl(gx)];
                v.y = orow[refl(gx + 1)];
            }
            *reinterpret_cast<float2*>(s_out + r * SW + pp * 2) = v;
            if ((unsigned)gy < (unsigned)Himg) {      // mean accumulate (zero-pad)
                float2 mo = *reinterpret_cast<float2*>(s_mean + r * SW + pp * 2);
                if ((unsigned)gx < (unsigned)Wimg)       mo.x += v.x;
                if ((unsigned)(gx + 1) < (unsigned)Wimg) mo.y += v.y;
                *reinterpret_cast<float2*>(s_mean + r * SW + pp * 2) = mo;
            }
        }
        __syncthreads();

        float bacc[4][4];
        #pragma unroll
        for (int i = 0; i < 4; ++i)
            #pragma unroll
            for (int j = 0; j < 4; ++j) bacc[i][j] = 0.0f;

        // horizontal 5-tap over 8 rows (4 outputs + 4 halo), vertical accumulate
        #pragma unroll
        for (int r = 0; r < 8; ++r) {
            const float4* rowp = reinterpret_cast<const float4*>(s_out) + (by + r) * (SW / 4);
            float4 a = rowp[tx];
            float4 b = rowp[tx + 1];
            float v[8] = {a.x, a.y, a.z, a.w, b.x, b.y, b.z, b.w};
            float hb[4];
            #pragma unroll
            for (int j = 0; j < 4; ++j)
                hb[j] = G0 * v[j] + G1 * v[j + 1] + G2 * v[j + 2]
                      + G1 * v[j + 3] + G0 * v[j + 4];
            #pragma unroll
            for (int i = 0; i < 4; ++i) {
                int k = r - i;
                if (k >= 0 && k <= 4) {
                    float w = gw[k];
                    #pragma unroll
                    for (int j = 0; j < 4; ++j) bacc[i][j] += w * hb[j];
                }
            }
        }

        const float* mc = ms + (n * Cc + c) * (Himg * Wimg);
        #pragma unroll
        for (int i = 0; i < 4; ++i) {
            float4 m4 = *reinterpret_cast<const float4*>(
                &mc[(y0 + by + i) * Wimg + x0 + bx]);
            acc_ms += fabsf(bacc[i][0] - m4.x) + fabsf(bacc[i][1] - m4.y)
                    + fabsf(bacc[i][2] - m4.z) + fabsf(bacc[i][3] - m4.w);
        }
    }

    __syncthreads();   // s_mean complete

    // ---- Sobel on channel-mean (=sum*0.125) vs pan, both zero-padded ----
    float acc_gx = 0.0f, acc_gy = 0.0f;
    #pragma unroll
    for (int i = 0; i < 4; ++i) {
        float m[3][8], p[3][8];
        #pragma unroll
        for (int dy = 0; dy < 3; ++dy) {
            int srow = by + i + 1 + dy;
            const float4* mr = reinterpret_cast<const float4*>(s_mean) + srow * (SW / 4);
            const float4* pr = reinterpret_cast<const float4*>(s_pan)  + srow * (SW / 4);
            float4 a = mr[tx], b = mr[tx + 1];
            m[dy][0]=a.x; m[dy][1]=a.y; m[dy][2]=a.z; m[dy][3]=a.w;
            m[dy][4]=b.x; m[dy][5]=b.y; m[dy][6]=b.z; m[dy][7]=b.w;
            float4 e = pr[tx], f = pr[tx + 1];
            p[dy][0]=e.x; p[dy][1]=e.y; p[dy][2]=e.z; p[dy][3]=e.w;
            p[dy][4]=f.x; p[dy][5]=f.y; p[dy][6]=f.z; p[dy][7]=f.w;
        }
        #pragma unroll
        for (int j = 0; j < 4; ++j) {
            float ogx = (m[0][j+3] + 2.0f*m[1][j+3] + m[2][j+3])
                      - (m[0][j+1] + 2.0f*m[1][j+1] + m[2][j+1]);
            float ogy = (m[2][j+1] + 2.0f*m[2][j+2] + m[2][j+3])
                      - (m[0][j+1] + 2.0f*m[0][j+2] + m[0][j+3]);
            float pgx = (p[0][j+3] + 2.0f*p[1][j+3] + p[2][j+3])
                      - (p[0][j+1] + 2.0f*p[1][j+1] + p[2][j+1]);
            float pgy = (p[2][j+1] + 2.0f*p[2][j+2] + p[2][j+3])
                      - (p[0][j+1] + 2.0f*p[0][j+2] + p[0][j+3]);
            acc_gx += fabsf(0.125f * ogx - pgx);
            acc_gy += fabsf(0.125f * ogy - pgy);
        }
    }

    // ---- block reduction -> per-block partials ----
    #pragma unroll
    for (int off = 16; off; off >>= 1) {
        acc_ms += __shfl_xor_sync(0xffffffffu, acc_ms, off);
        acc_gx += __shfl_xor_sync(0xffffffffu, acc_gx, off);
        acc_gy += __shfl_xor_sync(0xffffffffu, acc_gy, off);
    }
    int warp = tid >> 5, lane = tid & 31;
    if (lane == 0) {
        s_red[warp][0] = acc_ms; s_red[warp][1] = acc_gx; s_red[warp][2] = acc_gy;
    }
    __syncthreads();
    if (tid == 0) {
        float a = 0.0f, b = 0.0f, c2 = 0.0f;
        #pragma unroll
        for (int w = 0; w < 4; ++w) { a += s_red[w][0]; b += s_red[w][1]; c2 += s_red[w][2]; }
        int bid = (blockIdx.z * GY + blockIdx.y) * GX + blockIdx.x;
        g_part[bid * 3 + 0] = a;
        g_part[bid * 3 + 1] = b;
        g_part[bid * 3 + 2] = c2;
        __threadfence();                       // publish partials
        unsigned old = atomicAdd(&g_count, 1u);
        s_last = (old == (unsigned)(NBLK - 1));
    }
    __syncthreads();

    // ---- last arriving block performs the deterministic final reduction ----
    if (s_last) {
        __threadfence();   // acquire: see all partials
        float a = 0.0f, b = 0.0f, c = 0.0f;
        #pragma unroll
        for (int bblk = tid; bblk < NBLK; bblk += NTH) {   // fixed order per thread
            a += __ldcg(&g_part[bblk * 3 + 0]);
            b += __ldcg(&g_part[bblk * 3 + 1]);
            c += __ldcg(&g_part[bblk * 3 + 2]);
        }
        #pragma unroll
        for (int off = 16; off; off >>= 1) {
            a += __shfl_xor_sync(0xffffffffu, a, off);
            b += __shfl_xor_sync(0xffffffffu, b, off);
            c += __shfl_xor_sync(0xffffffffu, c, off);
        }
        if (lane == 0) { s_red[warp][0] = a; s_red[warp][1] = b; s_red[warp][2] = c; }
        __syncthreads();
        if (tid == 0) {
            float fa = 0.0f, fb = 0.0f, fc = 0.0f;
            #pragma unroll
            for (int w = 0; w < 4; ++w) { fa += s_red[w][0]; fb += s_red[w][1]; fc += s_red[w][2]; }
            // loss = acc_ms / (N*C*H*W) + (acc_gx + acc_gy) / (N*H*W)
            lossp[0] = fa * (1.0f / 16777216.0f) + (fb + fc) * (1.0f / 2097152.0f);
            g_count = 0;                      // reset for next graph replay
        }
    }
}

extern "C" void kernel_launch(void* const* d_in, const int* in_sizes, int n_in,
                              void* d_out, int out_size)
{
    // Expected order: pan [2097152], ms [16777216], out [16777216].
    // Defensive: locate pan by its unique size; the two big tensors keep order ms, out.
    const float* pan = (const float*)d_in[0];
    const float* ms  = (const float*)d_in[1];
    const float* outp= (const float*)d_in[2];
    if (n_in == 3 && in_sizes[0] != 2097152) {
        const float* big[2]; int nb = 0;
        for (int i = 0; i < 3; ++i) {
            if (in_sizes[i] == 2097152) pan = (const float*)d_in[i];
            else if (nb < 2) big[nb++] = (const float*)d_in[i];
        }
        if (nb == 2) { ms = big[0]; outp = big[1]; }
    }

    dim3 grid(GX, GY, Nb);
    loss_main_kernel<<<grid, NTH>>>(pan, ms, outp, (float*)d_out);
}